// round 1
// baseline (speedup 1.0000x reference)
#include <cuda_runtime.h>
#include <cuda_bf16.h>

// Problem constants
#define EMBED   1024
#define NHEAD   16
#define HDIM    64
#define BATCH   4
#define SEQ     2048
#define MROWS   (BATCH * SEQ)        // 8192

// Scratch (device globals — allocation inside kernel_launch is forbidden)
__device__ float g_q [BATCH * NHEAD * SEQ * HDIM];   // [B,H,T,D]
__device__ float g_k [BATCH * NHEAD * SEQ * HDIM];
__device__ float g_v [BATCH * NHEAD * SEQ * HDIM];
__device__ float g_ao[MROWS * EMBED];                // attention out, [B*T, C]

// ---------------------------------------------------------------------------
// GEMM: C = A @ B^T.  A: [M,K] row-major, B: [N,K] row-major.
// Block tile 128x128, K-tile 16, 256 threads, 8x8 per thread.
// MODE 0: plain store C[M,N] row-major.
// MODE 1: scatter QKV epilogue into g_q/g_k/g_v with [B,H,T,D] layout.
// ---------------------------------------------------------------------------
template <int MODE>
__global__ void __launch_bounds__(256)
gemm_nt(const float* __restrict__ A, const float* __restrict__ B,
        float* __restrict__ C, int K, int N)
{
    __shared__ float As[16][132];
    __shared__ float Bs[16][132];

    const int tid  = threadIdx.x;
    const int row0 = blockIdx.y * 128;
    const int col0 = blockIdx.x * 128;

    const int tx = tid & 15;       // 0..15
    const int ty = tid >> 4;       // 0..15
    const int tx8 = tx * 8;
    const int ty8 = ty * 8;

    const int ldRow = tid >> 2;    // 0..63
    const int ldK4  = tid & 3;     // 0..3

    const float* Ap = A + (size_t)row0 * K;
    const float* Bp = B + (size_t)col0 * K;

    float acc[8][8];
#pragma unroll
    for (int i = 0; i < 8; i++)
#pragma unroll
        for (int j = 0; j < 8; j++) acc[i][j] = 0.f;

    for (int kt = 0; kt < K; kt += 16) {
#pragma unroll
        for (int p = 0; p < 2; p++) {
            int r = ldRow + p * 64;
            float4 a = *(const float4*)&Ap[(size_t)r * K + kt + ldK4 * 4];
            As[ldK4 * 4 + 0][r] = a.x;
            As[ldK4 * 4 + 1][r] = a.y;
            As[ldK4 * 4 + 2][r] = a.z;
            As[ldK4 * 4 + 3][r] = a.w;
            float4 b = *(const float4*)&Bp[(size_t)r * K + kt + ldK4 * 4];
            Bs[ldK4 * 4 + 0][r] = b.x;
            Bs[ldK4 * 4 + 1][r] = b.y;
            Bs[ldK4 * 4 + 2][r] = b.z;
            Bs[ldK4 * 4 + 3][r] = b.w;
        }
        __syncthreads();

#pragma unroll
        for (int kk = 0; kk < 16; kk++) {
            float4 a0 = *(const float4*)&As[kk][ty8];
            float4 a1 = *(const float4*)&As[kk][ty8 + 4];
            float4 b0 = *(const float4*)&Bs[kk][tx8];
            float4 b1 = *(const float4*)&Bs[kk][tx8 + 4];
            float av[8] = {a0.x, a0.y, a0.z, a0.w, a1.x, a1.y, a1.z, a1.w};
            float bv[8] = {b0.x, b0.y, b0.z, b0.w, b1.x, b1.y, b1.z, b1.w};
#pragma unroll
            for (int i = 0; i < 8; i++)
#pragma unroll
                for (int j = 0; j < 8; j++)
                    acc[i][j] += av[i] * bv[j];
        }
        __syncthreads();
    }

    if (MODE == 0) {
        // plain row-major C [M,N]
#pragma unroll
        for (int i = 0; i < 8; i++) {
            int r = row0 + ty8 + i;
            float* cp = C + (size_t)r * N + col0 + tx8;
            float4 v0 = make_float4(acc[i][0], acc[i][1], acc[i][2], acc[i][3]);
            float4 v1 = make_float4(acc[i][4], acc[i][5], acc[i][6], acc[i][7]);
            *(float4*)(cp)     = v0;
            *(float4*)(cp + 4) = v1;
        }
    } else {
        // scatter: n in [0,3072): sec = n/1024 (q/k/v), c = n%1024, h = c/64, d = c%64
        // m: b = m/SEQ, t = m%SEQ.  dst[((b*NHEAD+h)*SEQ + t)*HDIM + d]
#pragma unroll
        for (int i = 0; i < 8; i++) {
            int m = row0 + ty8 + i;
            int b = m >> 11;           // /2048
            int t = m & (SEQ - 1);
#pragma unroll
            for (int j = 0; j < 8; j++) {
                int n   = col0 + tx8 + j;
                int sec = n >> 10;
                int c   = n & 1023;
                int h   = c >> 6;
                int d   = c & 63;
                float* buf = (sec == 0) ? g_q : (sec == 1) ? g_k : g_v;
                buf[(((size_t)(b * NHEAD + h)) * SEQ + t) * HDIM + d] = acc[i][j];
            }
        }
    }
}

// ---------------------------------------------------------------------------
// Causal flash attention, fp32. Br = Bc = 64, D = 64.
// Block: 256 threads as 16x16; each thread owns 4 rows x 4 cols.
// grid: (SEQ/64, B*H)
// ---------------------------------------------------------------------------
#define ATT_STRIDE 68
#define ATT_SMEM   (4 * 64 * ATT_STRIDE * 4)   // Qs, Ks, Vs, Ps

__global__ void __launch_bounds__(256)
attn_kernel()
{
    extern __shared__ float sm[];
    float* Qs = sm;
    float* Ks = Qs + 64 * ATT_STRIDE;
    float* Vs = Ks + 64 * ATT_STRIDE;
    float* Ps = Vs + 64 * ATT_STRIDE;

    const int qt = blockIdx.x;            // q tile (0..31)
    const int bh = blockIdx.y;            // 0..63
    const int b  = bh / NHEAD;
    const int h  = bh % NHEAD;

    const float* Qb = g_q + (size_t)bh * SEQ * HDIM;
    const float* Kb = g_k + (size_t)bh * SEQ * HDIM;
    const float* Vb = g_v + (size_t)bh * SEQ * HDIM;

    const int tid = threadIdx.x;
    const int tx  = tid & 15;
    const int ty  = tid >> 4;
    const int q0  = qt * 64;

    // load Q tile, pre-scaled by 1/sqrt(D)
    for (int idx = tid; idx < 64 * 64; idx += 256) {
        int r = idx >> 6, c = idx & 63;
        Qs[r * ATT_STRIDE + c] = Qb[(size_t)(q0 + r) * HDIM + c] * 0.125f;
    }

    float O_[4][4];
    float mrow[4], lrow[4];
#pragma unroll
    for (int i = 0; i < 4; i++) {
        mrow[i] = -1e30f;
        lrow[i] = 0.f;
#pragma unroll
        for (int c = 0; c < 4; c++) O_[i][c] = 0.f;
    }

    for (int kt = 0; kt <= qt; kt++) {
        __syncthreads();     // protect K/V/P against prior-iteration readers
        const int k0 = kt * 64;
        for (int idx = tid; idx < 64 * 64; idx += 256) {
            int r = idx >> 6, c = idx & 63;
            Ks[r * ATT_STRIDE + c] = Kb[(size_t)(k0 + r) * HDIM + c];
            Vs[r * ATT_STRIDE + c] = Vb[(size_t)(k0 + r) * HDIM + c];
        }
        __syncthreads();

        // S = Q K^T (4x4 per thread)
        float s[4][4];
#pragma unroll
        for (int i = 0; i < 4; i++)
#pragma unroll
            for (int j = 0; j < 4; j++) s[i][j] = 0.f;

#pragma unroll
        for (int d4 = 0; d4 < 16; d4++) {
            float4 q[4], k[4];
#pragma unroll
            for (int i = 0; i < 4; i++)
                q[i] = *(const float4*)&Qs[(ty * 4 + i) * ATT_STRIDE + d4 * 4];
#pragma unroll
            for (int j = 0; j < 4; j++)
                k[j] = *(const float4*)&Ks[(tx * 4 + j) * ATT_STRIDE + d4 * 4];
#pragma unroll
            for (int i = 0; i < 4; i++)
#pragma unroll
                for (int j = 0; j < 4; j++)
                    s[i][j] += q[i].x * k[j].x + q[i].y * k[j].y +
                               q[i].z * k[j].z + q[i].w * k[j].w;
        }

        // causal mask (only the diagonal tile needs it)
        if (kt == qt) {
#pragma unroll
            for (int i = 0; i < 4; i++) {
                int qg = q0 + ty * 4 + i;
#pragma unroll
                for (int j = 0; j < 4; j++) {
                    int kg = k0 + tx * 4 + j;
                    if (kg > qg) s[i][j] = -1e30f;
                }
            }
        }

        // online softmax per row (row group = 16 threads sharing ty)
#pragma unroll
        for (int i = 0; i < 4; i++) {
            float mx = fmaxf(fmaxf(s[i][0], s[i][1]), fmaxf(s[i][2], s[i][3]));
#pragma unroll
            for (int off = 8; off >= 1; off >>= 1)
                mx = fmaxf(mx, __shfl_xor_sync(0xffffffffu, mx, off, 16));
            float newm = fmaxf(mrow[i], mx);

            float p[4], psum = 0.f;
#pragma unroll
            for (int j = 0; j < 4; j++) {
                p[j] = __expf(s[i][j] - newm);
                psum += p[j];
            }
#pragma unroll
            for (int off = 8; off >= 1; off >>= 1)
                psum += __shfl_xor_sync(0xffffffffu, psum, off, 16);

            float f = __expf(mrow[i] - newm);
            lrow[i] = lrow[i] * f + psum;
            mrow[i] = newm;
#pragma unroll
            for (int c = 0; c < 4; c++) O_[i][c] *= f;
#pragma unroll
            for (int j = 0; j < 4; j++)
                Ps[(ty * 4 + i) * ATT_STRIDE + tx * 4 + j] = p[j];
        }
        __syncthreads();

        // O += P @ V
#pragma unroll
        for (int j4 = 0; j4 < 16; j4++) {
            float4 p[4], v[4];
#pragma unroll
            for (int i = 0; i < 4; i++)
                p[i] = *(const float4*)&Ps[(ty * 4 + i) * ATT_STRIDE + j4 * 4];
#pragma unroll
            for (int jj = 0; jj < 4; jj++)
                v[jj] = *(const float4*)&Vs[(j4 * 4 + jj) * ATT_STRIDE + tx * 4];
#pragma unroll
            for (int i = 0; i < 4; i++) {
                O_[i][0] += p[i].x * v[0].x + p[i].y * v[1].x + p[i].z * v[2].x + p[i].w * v[3].x;
                O_[i][1] += p[i].x * v[0].y + p[i].y * v[1].y + p[i].z * v[2].y + p[i].w * v[3].y;
                O_[i][2] += p[i].x * v[0].z + p[i].y * v[1].z + p[i].z * v[2].z + p[i].w * v[3].z;
                O_[i][3] += p[i].x * v[0].w + p[i].y * v[1].w + p[i].z * v[2].w + p[i].w * v[3].w;
            }
        }
    }

    // final normalize + write to g_ao in [B*T, C] layout: col = h*64 + d
#pragma unroll
    for (int i = 0; i < 4; i++) {
        float inv = 1.0f / lrow[i];
        int t = q0 + ty * 4 + i;
        float* op = g_ao + ((size_t)(b * SEQ + t)) * EMBED + h * HDIM + tx * 4;
        float4 o = make_float4(O_[i][0] * inv, O_[i][1] * inv,
                               O_[i][2] * inv, O_[i][3] * inv);
        *(float4*)op = o;
    }
}

// ---------------------------------------------------------------------------
extern "C" void kernel_launch(void* const* d_in, const int* in_sizes, int n_in,
                              void* d_out, int out_size)
{
    const float* x      = (const float*)d_in[0];   // [4,2048,1024]
    const float* W_qkv  = (const float*)d_in[1];   // [3072,1024]
    const float* W_proj = (const float*)d_in[2];   // [1024,1024]
    float* out = (float*)d_out;                    // [4,2048,1024]

    // 1) QKV projection with scatter into g_q/g_k/g_v
    {
        dim3 grid(3072 / 128, MROWS / 128);
        gemm_nt<1><<<grid, 256>>>(x, W_qkv, nullptr, EMBED, 3 * EMBED);
    }

    // 2) causal flash attention -> g_ao
    {
        cudaFuncSetAttribute((const void*)attn_kernel,
                             cudaFuncAttributeMaxDynamicSharedMemorySize,
                             ATT_SMEM);
        dim3 grid(SEQ / 64, BATCH * NHEAD);
        attn_kernel<<<grid, 256, ATT_SMEM>>>();
    }

    // 3) output projection -> d_out
    {
        float* ao_ptr = nullptr;
        cudaGetSymbolAddress((void**)&ao_ptr, g_ao);
        dim3 grid(EMBED / 128, MROWS / 128);
        gemm_nt<0><<<grid, 256>>>(ao_ptr, W_proj, out, EMBED, EMBED);
    }
}

// round 2
// speedup vs baseline: 3.7786x; 3.7786x over previous
#include <cuda_runtime.h>
#include <cuda_bf16.h>
#include <cstdint>

// Problem constants
#define EMBED   1024
#define NHEAD   16
#define HDIM    64
#define BATCH   4
#define SEQ     2048
#define MROWS   (BATCH * SEQ)        // 8192

// Scratch (device globals — allocation inside kernel_launch is forbidden)
__device__ float g_q [BATCH * NHEAD * SEQ * HDIM];   // [B,H,T,D]
__device__ float g_k [BATCH * NHEAD * SEQ * HDIM];
__device__ float g_v [BATCH * NHEAD * SEQ * HDIM];
__device__ float g_ao[MROWS * EMBED];                // attention out, [B*T, C]

// ---------------------------------------------------------------------------
// helpers
// ---------------------------------------------------------------------------
__device__ __forceinline__ uint32_t f2tf32(float x) {
    uint32_t r;
    asm("cvt.rna.tf32.f32 %0, %1;" : "=r"(r) : "f"(x));
    return r;
}
__device__ __forceinline__ void dec_tf32(float x, uint32_t& hi, uint32_t& lo) {
    asm("cvt.rna.tf32.f32 %0, %1;" : "=r"(hi) : "f"(x));
    float r = x - __uint_as_float(hi);
    asm("cvt.rna.tf32.f32 %0, %1;" : "=r"(lo) : "f"(r));
}
__device__ __forceinline__ void mma_tf32(float* c, const uint32_t* a, const uint32_t* b) {
    asm volatile(
        "mma.sync.aligned.m16n8k8.row.col.f32.tf32.tf32.f32 "
        "{%0,%1,%2,%3}, {%4,%5,%6,%7}, {%8,%9}, {%0,%1,%2,%3};"
        : "+f"(c[0]), "+f"(c[1]), "+f"(c[2]), "+f"(c[3])
        : "r"(a[0]), "r"(a[1]), "r"(a[2]), "r"(a[3]), "r"(b[0]), "r"(b[1]));
}
__device__ __forceinline__ void cpasync16(void* s, const void* g) {
    uint32_t sa = (uint32_t)__cvta_generic_to_shared(s);
    asm volatile("cp.async.cg.shared.global [%0], [%1], 16;\n" :: "r"(sa), "l"(g));
}
#define CP_COMMIT() asm volatile("cp.async.commit_group;\n" ::: "memory")
#define CP_WAIT1()  asm volatile("cp.async.wait_group 1;\n"  ::: "memory")
#define CP_WAIT0()  asm volatile("cp.async.wait_group 0;\n"  ::: "memory")

// ---------------------------------------------------------------------------
// TF32 tensor-core GEMM:  C = A @ B^T.  A:[M,K] rm, B:[N,K] rm.
// Block tile 128x128, kTile 32, 256 threads (8 warps, warp tile 32x64).
// COMP=1: 3xTF32 compensated (hi*hi + hi*lo + lo*hi)   — fp32-like accuracy
// MODE=1: QKV scatter epilogue into g_q/g_k/g_v ([B,H,T,D])
// ---------------------------------------------------------------------------
#define GS 36                            // smem row stride (floats), pad 4
#define GEMM_SMEM (2 * 2 * 128 * GS * 4) // 73728 bytes

template <int MODE, int COMP>
__global__ void __launch_bounds__(256)
gemm_tf32(const float* __restrict__ A, const float* __restrict__ B,
          float* __restrict__ C, int K, int N)
{
    extern __shared__ float sm[];
    float* As = sm;                      // [2][128][GS]
    float* Bs = sm + 2 * 128 * GS;       // [2][128][GS]

    const int tid  = threadIdx.x;
    const int lane = tid & 31;
    const int w    = tid >> 5;
    const int gr   = lane >> 2;          // 0..7
    const int tig  = lane & 3;           // 0..3
    const int wm   = w & 3;              // m quadrant (32 rows)
    const int wn   = w >> 2;             // n half   (64 cols)

    const int row0 = blockIdx.y * 128;
    const int col0 = blockIdx.x * 128;

    float acc[2][8][4];
#pragma unroll
    for (int i = 0; i < 2; i++)
#pragma unroll
        for (int j = 0; j < 8; j++)
#pragma unroll
            for (int e = 0; e < 4; e++) acc[i][j][e] = 0.f;

    // ---- async tile loader: 128 rows x 32 floats per matrix per stage
    auto loadTile = [&](int s, int kt) {
#pragma unroll
        for (int p = 0; p < 4; p++) {
            int i   = tid + 256 * p;
            int row = i >> 3;
            int c4  = (i & 7) * 4;
            cpasync16(&As[(size_t)s * 128 * GS + row * GS + c4],
                      &A[(size_t)(row0 + row) * K + kt + c4]);
            cpasync16(&Bs[(size_t)s * 128 * GS + row * GS + c4],
                      &B[(size_t)(col0 + row) * K + kt + c4]);
        }
    };

    const int nk = K / 32;
    loadTile(0, 0);  CP_COMMIT();
    loadTile(1, 32); CP_COMMIT();

    for (int t = 0; t < nk; t++) {
        const int s = t & 1;
        if (t >= nk - 2) { CP_WAIT0(); } else { CP_WAIT1(); }
        __syncthreads();

        const float* as = As + (size_t)s * 128 * GS;
        const float* bs = Bs + (size_t)s * 128 * GS;

#pragma unroll
        for (int ks = 0; ks < 4; ks++) {
            uint32_t ah[2][4], al[2][4];
#pragma unroll
            for (int mt = 0; mt < 2; mt++) {
                int r = wm * 32 + mt * 16 + gr;
                float x0 = as[(r    ) * GS + ks * 8 + tig];
                float x1 = as[(r + 8) * GS + ks * 8 + tig];
                float x2 = as[(r    ) * GS + ks * 8 + tig + 4];
                float x3 = as[(r + 8) * GS + ks * 8 + tig + 4];
                if (COMP) {
                    dec_tf32(x0, ah[mt][0], al[mt][0]);
                    dec_tf32(x1, ah[mt][1], al[mt][1]);
                    dec_tf32(x2, ah[mt][2], al[mt][2]);
                    dec_tf32(x3, ah[mt][3], al[mt][3]);
                } else {
                    ah[mt][0] = f2tf32(x0); ah[mt][1] = f2tf32(x1);
                    ah[mt][2] = f2tf32(x2); ah[mt][3] = f2tf32(x3);
                }
            }
            uint32_t bh[8][2], bl[8][2];
#pragma unroll
            for (int nt = 0; nt < 8; nt++) {
                int cn = wn * 64 + nt * 8 + gr;
                float y0 = bs[cn * GS + ks * 8 + tig];
                float y1 = bs[cn * GS + ks * 8 + tig + 4];
                if (COMP) {
                    dec_tf32(y0, bh[nt][0], bl[nt][0]);
                    dec_tf32(y1, bh[nt][1], bl[nt][1]);
                } else {
                    bh[nt][0] = f2tf32(y0); bh[nt][1] = f2tf32(y1);
                }
            }
#pragma unroll
            for (int mt = 0; mt < 2; mt++)
#pragma unroll
                for (int nt = 0; nt < 8; nt++) {
                    mma_tf32(acc[mt][nt], ah[mt], bh[nt]);
                    if (COMP) {
                        mma_tf32(acc[mt][nt], ah[mt], bl[nt]);
                        mma_tf32(acc[mt][nt], al[mt], bh[nt]);
                    }
                }
        }
        __syncthreads();
        if (t + 2 < nk) { loadTile(s, (t + 2) * 32); CP_COMMIT(); }
    }

    // ---- epilogue
#pragma unroll
    for (int mt = 0; mt < 2; mt++) {
#pragma unroll
        for (int e2 = 0; e2 < 2; e2++) {          // row sub: gr / gr+8
            int r = row0 + wm * 32 + mt * 16 + gr + e2 * 8;
#pragma unroll
            for (int nt = 0; nt < 8; nt++) {
                int n = col0 + wn * 64 + nt * 8 + 2 * tig;
                float v0 = acc[mt][nt][e2 * 2 + 0];
                float v1 = acc[mt][nt][e2 * 2 + 1];
                if (MODE == 0) {
                    *(float2*)&C[(size_t)r * N + n] = make_float2(v0, v1);
                } else {
                    int b   = r >> 11;            // / SEQ
                    int tk  = r & (SEQ - 1);
                    int sec = n >> 10;
                    int c   = n & 1023;
                    int h   = c >> 6;
                    int d   = c & 63;
                    float* buf = (sec == 0) ? g_q : (sec == 1) ? g_k : g_v;
                    *(float2*)&buf[(((size_t)(b * NHEAD + h)) * SEQ + tk) * HDIM + d] =
                        make_float2(v0, v1);
                }
            }
        }
    }
}

// ---------------------------------------------------------------------------
// Causal flash attention with TF32 mma. Br=128, Bc=64, D=64.
// 256 threads = 8 warps; warp w owns q rows [16w, 16w+16).
// grid: (SEQ/128, B*H)
// ---------------------------------------------------------------------------
#define AS 72                                    // smem row stride (floats)
#define ATT_SMEM ((128 + 64 + 64) * AS * 4)      // QP + Ks + Vs = 73728

__global__ void __launch_bounds__(256)
attn_mma()
{
    extern __shared__ float sm[];
    float* QP = sm;                  // [128][AS]  Q tile, reused for P
    float* Ks = sm + 128 * AS;       // [64][AS]
    float* Vs = Ks + 64 * AS;        // [64][AS]

    const int tid  = threadIdx.x;
    const int lane = tid & 31;
    const int w    = tid >> 5;
    const int gr   = lane >> 2;
    const int tig  = lane & 3;
    const int m0   = w * 16;

    const int qb = blockIdx.x;
    const int bh = blockIdx.y;
    const int b  = bh >> 4;
    const int h  = bh & 15;
    const int q0 = qb * 128;

    const float* Qb = g_q + (size_t)bh * SEQ * HDIM;
    const float* Kb = g_k + (size_t)bh * SEQ * HDIM;
    const float* Vb = g_v + (size_t)bh * SEQ * HDIM;

    // ---- load Q tile (scaled by 1/sqrt(D)) and build A fragments
    for (int i = tid; i < 128 * 16; i += 256) {
        int row = i >> 4;
        int c4  = (i & 15) * 4;
        float4 v = *(const float4*)&Qb[(size_t)(q0 + row) * HDIM + c4];
        v.x *= 0.125f; v.y *= 0.125f; v.z *= 0.125f; v.w *= 0.125f;
        *(float4*)&QP[row * AS + c4] = v;
    }
    __syncthreads();

    uint32_t qf[8][4];
#pragma unroll
    for (int dk = 0; dk < 8; dk++) {
        qf[dk][0] = f2tf32(QP[(m0 + gr    ) * AS + dk * 8 + tig]);
        qf[dk][1] = f2tf32(QP[(m0 + gr + 8) * AS + dk * 8 + tig]);
        qf[dk][2] = f2tf32(QP[(m0 + gr    ) * AS + dk * 8 + tig + 4]);
        qf[dk][3] = f2tf32(QP[(m0 + gr + 8) * AS + dk * 8 + tig + 4]);
    }
    __syncthreads();   // QP now free for P

    float o[8][4];
#pragma unroll
    for (int nt = 0; nt < 8; nt++)
#pragma unroll
        for (int e = 0; e < 4; e++) o[nt][e] = 0.f;
    float mrow[2] = {-1e30f, -1e30f};
    float lrow[2] = {0.f, 0.f};

    const int ktmax = 2 * qb + 1;
    for (int kt = 0; kt <= ktmax; kt++) {
        __syncthreads();     // protect Ks/Vs/QP(P) from previous iteration
        const int k0 = kt * 64;
        for (int i = tid; i < 64 * 16; i += 256) {
            int row = i >> 4;
            int c4  = (i & 15) * 4;
            *(float4*)&Ks[row * AS + c4] = *(const float4*)&Kb[(size_t)(k0 + row) * HDIM + c4];
            *(float4*)&Vs[row * AS + c4] = *(const float4*)&Vb[(size_t)(k0 + row) * HDIM + c4];
        }
        __syncthreads();

        // ---- S = Q K^T
        float sfr[8][4];
#pragma unroll
        for (int nt = 0; nt < 8; nt++)
#pragma unroll
            for (int e = 0; e < 4; e++) sfr[nt][e] = 0.f;

#pragma unroll
        for (int dk = 0; dk < 8; dk++) {
            uint32_t kf[8][2];
#pragma unroll
            for (int nt = 0; nt < 8; nt++) {
                kf[nt][0] = f2tf32(Ks[(nt * 8 + gr) * AS + dk * 8 + tig]);
                kf[nt][1] = f2tf32(Ks[(nt * 8 + gr) * AS + dk * 8 + tig + 4]);
            }
#pragma unroll
            for (int nt = 0; nt < 8; nt++)
                mma_tf32(sfr[nt], qf[dk], kf[nt]);
        }

        // ---- causal mask (only needed near the diagonal)
        if (k0 + 63 > q0 + m0) {
#pragma unroll
            for (int nt = 0; nt < 8; nt++)
#pragma unroll
                for (int e = 0; e < 4; e++) {
                    int rg = q0 + m0 + gr + (e >> 1) * 8;
                    int cg = k0 + nt * 8 + 2 * tig + (e & 1);
                    if (cg > rg) sfr[nt][e] = -1e30f;
                }
        }

        // ---- online softmax (thread rows: gr, gr+8)
        float mx0 = -1e30f, mx1 = -1e30f;
#pragma unroll
        for (int nt = 0; nt < 8; nt++) {
            mx0 = fmaxf(mx0, fmaxf(sfr[nt][0], sfr[nt][1]));
            mx1 = fmaxf(mx1, fmaxf(sfr[nt][2], sfr[nt][3]));
        }
        mx0 = fmaxf(mx0, __shfl_xor_sync(0xffffffffu, mx0, 1));
        mx0 = fmaxf(mx0, __shfl_xor_sync(0xffffffffu, mx0, 2));
        mx1 = fmaxf(mx1, __shfl_xor_sync(0xffffffffu, mx1, 1));
        mx1 = fmaxf(mx1, __shfl_xor_sync(0xffffffffu, mx1, 2));

        float nm0 = fmaxf(mrow[0], mx0);
        float nm1 = fmaxf(mrow[1], mx1);
        float f0  = __expf(mrow[0] - nm0);
        float f1  = __expf(mrow[1] - nm1);

        float ps0 = 0.f, ps1 = 0.f;
#pragma unroll
        for (int nt = 0; nt < 8; nt++) {
            float p0 = __expf(sfr[nt][0] - nm0);
            float p1 = __expf(sfr[nt][1] - nm0);
            float p2 = __expf(sfr[nt][2] - nm1);
            float p3 = __expf(sfr[nt][3] - nm1);
            ps0 += p0 + p1;
            ps1 += p2 + p3;
            *(float2*)&QP[(m0 + gr    ) * AS + nt * 8 + 2 * tig] = make_float2(p0, p1);
            *(float2*)&QP[(m0 + gr + 8) * AS + nt * 8 + 2 * tig] = make_float2(p2, p3);
        }
        ps0 += __shfl_xor_sync(0xffffffffu, ps0, 1);
        ps0 += __shfl_xor_sync(0xffffffffu, ps0, 2);
        ps1 += __shfl_xor_sync(0xffffffffu, ps1, 1);
        ps1 += __shfl_xor_sync(0xffffffffu, ps1, 2);

        lrow[0] = lrow[0] * f0 + ps0;
        lrow[1] = lrow[1] * f1 + ps1;
        mrow[0] = nm0;
        mrow[1] = nm1;
#pragma unroll
        for (int nt = 0; nt < 8; nt++) {
            o[nt][0] *= f0; o[nt][1] *= f0;
            o[nt][2] *= f1; o[nt][3] *= f1;
        }
        __syncwarp();

        // ---- O += P V   (P: m16 x k64 from own smem rows; V: [k][d])
#pragma unroll
        for (int kk = 0; kk < 8; kk++) {
            uint32_t pf[4];
            pf[0] = f2tf32(QP[(m0 + gr    ) * AS + kk * 8 + tig]);
            pf[1] = f2tf32(QP[(m0 + gr + 8) * AS + kk * 8 + tig]);
            pf[2] = f2tf32(QP[(m0 + gr    ) * AS + kk * 8 + tig + 4]);
            pf[3] = f2tf32(QP[(m0 + gr + 8) * AS + kk * 8 + tig + 4]);
            uint32_t vf[8][2];
#pragma unroll
            for (int nt = 0; nt < 8; nt++) {
                vf[nt][0] = f2tf32(Vs[(kk * 8 + tig    ) * AS + nt * 8 + gr]);
                vf[nt][1] = f2tf32(Vs[(kk * 8 + tig + 4) * AS + nt * 8 + gr]);
            }
#pragma unroll
            for (int nt = 0; nt < 8; nt++)
                mma_tf32(o[nt], pf, vf[nt]);
        }
    }

    // ---- normalize and store to g_ao [B*T, C]
    float inv0 = 1.0f / lrow[0];
    float inv1 = 1.0f / lrow[1];
    int r0 = q0 + m0 + gr;
#pragma unroll
    for (int nt = 0; nt < 8; nt++) {
        int d = h * HDIM + nt * 8 + 2 * tig;
        *(float2*)&g_ao[(size_t)(b * SEQ + r0) * EMBED + d] =
            make_float2(o[nt][0] * inv0, o[nt][1] * inv0);
        *(float2*)&g_ao[(size_t)(b * SEQ + r0 + 8) * EMBED + d] =
            make_float2(o[nt][2] * inv1, o[nt][3] * inv1);
    }
}

// ---------------------------------------------------------------------------
extern "C" void kernel_launch(void* const* d_in, const int* in_sizes, int n_in,
                              void* d_out, int out_size)
{
    const float* x      = (const float*)d_in[0];   // [4,2048,1024]
    const float* W_qkv  = (const float*)d_in[1];   // [3072,1024]
    const float* W_proj = (const float*)d_in[2];   // [1024,1024]
    float* out = (float*)d_out;                    // [4,2048,1024]

    // 1) QKV projection (3xTF32 compensated) with scatter into g_q/g_k/g_v
    {
        cudaFuncSetAttribute((const void*)gemm_tf32<1, 1>,
                             cudaFuncAttributeMaxDynamicSharedMemorySize, GEMM_SMEM);
        dim3 grid(3 * EMBED / 128, MROWS / 128);
        gemm_tf32<1, 1><<<grid, 256, GEMM_SMEM>>>(x, W_qkv, nullptr, EMBED, 3 * EMBED);
    }

    // 2) causal flash attention (tf32 mma) -> g_ao
    {
        cudaFuncSetAttribute((const void*)attn_mma,
                             cudaFuncAttributeMaxDynamicSharedMemorySize, ATT_SMEM);
        dim3 grid(SEQ / 128, BATCH * NHEAD);
        attn_mma<<<grid, 256, ATT_SMEM>>>();
    }

    // 3) output projection (single-pass tf32) -> d_out
    {
        cudaFuncSetAttribute((const void*)gemm_tf32<0, 0>,
                             cudaFuncAttributeMaxDynamicSharedMemorySize, GEMM_SMEM);
        float* ao_ptr = nullptr;
        cudaGetSymbolAddress((void**)&ao_ptr, g_ao);
        dim3 grid(EMBED / 128, MROWS / 128);
        gemm_tf32<0, 0><<<grid, 256, GEMM_SMEM>>>(ao_ptr, W_proj, out, EMBED, EMBED);
    }
}

// round 3
// speedup vs baseline: 4.3457x; 1.1501x over previous
#include <cuda_runtime.h>
#include <cuda_bf16.h>
#include <cstdint>

// Problem constants
#define EMBED   1024
#define NHEAD   16
#define HDIM    64
#define BATCH   4
#define SEQ     2048
#define MROWS   (BATCH * SEQ)                 // 8192
#define QKVN    (BATCH * NHEAD * SEQ * HDIM)  // 8388608

// ---------------------------------------------------------------------------
// Persistent scratch (bf16 hi/lo split everywhere)
// ---------------------------------------------------------------------------
__device__ __align__(16) __nv_bfloat16 g_xh [MROWS * EMBED];
__device__ __align__(16) __nv_bfloat16 g_xl [MROWS * EMBED];
__device__ __align__(16) __nv_bfloat16 g_wqh[3 * EMBED * EMBED];
__device__ __align__(16) __nv_bfloat16 g_wql[3 * EMBED * EMBED];
__device__ __align__(16) __nv_bfloat16 g_wph[EMBED * EMBED];
__device__ __align__(16) __nv_bfloat16 g_wpl[EMBED * EMBED];
__device__ __align__(16) __nv_bfloat16 g_qh [QKVN];   // [B,H,T,D]
__device__ __align__(16) __nv_bfloat16 g_ql [QKVN];
__device__ __align__(16) __nv_bfloat16 g_kh [QKVN];   // [B,H,T,D]
__device__ __align__(16) __nv_bfloat16 g_kl [QKVN];
__device__ __align__(16) __nv_bfloat16 g_vth[QKVN];   // [B,H,D,T]  (transposed!)
__device__ __align__(16) __nv_bfloat16 g_vtl[QKVN];
__device__ __align__(16) __nv_bfloat16 g_aoh[MROWS * EMBED];   // [B*T, C]
__device__ __align__(16) __nv_bfloat16 g_aol[MROWS * EMBED];

// ---------------------------------------------------------------------------
// helpers
// ---------------------------------------------------------------------------
__device__ __forceinline__ void mma_bf16(float* c, const uint32_t* a, const uint32_t* b) {
    asm volatile(
        "mma.sync.aligned.m16n8k16.row.col.f32.bf16.bf16.f32 "
        "{%0,%1,%2,%3}, {%4,%5,%6,%7}, {%8,%9}, {%0,%1,%2,%3};"
        : "+f"(c[0]), "+f"(c[1]), "+f"(c[2]), "+f"(c[3])
        : "r"(a[0]), "r"(a[1]), "r"(a[2]), "r"(a[3]), "r"(b[0]), "r"(b[1]));
}
__device__ __forceinline__ void splitpack(float x0, float x1, uint32_t& hp, uint32_t& lp) {
    __nv_bfloat16 h0 = __float2bfloat16_rn(x0);
    __nv_bfloat16 h1 = __float2bfloat16_rn(x1);
    __nv_bfloat16 l0 = __float2bfloat16_rn(x0 - __bfloat162float(h0));
    __nv_bfloat16 l1 = __float2bfloat16_rn(x1 - __bfloat162float(h1));
    hp = (uint32_t)__bfloat16_as_ushort(h0) | ((uint32_t)__bfloat16_as_ushort(h1) << 16);
    lp = (uint32_t)__bfloat16_as_ushort(l0) | ((uint32_t)__bfloat16_as_ushort(l1) << 16);
}
__device__ __forceinline__ void cpasync16(void* s, const void* g) {
    uint32_t sa = (uint32_t)__cvta_generic_to_shared(s);
    asm volatile("cp.async.cg.shared.global [%0], [%1], 16;\n" :: "r"(sa), "l"(g));
}
#define CP_COMMIT() asm volatile("cp.async.commit_group;\n" ::: "memory")
#define CP_WAIT1()  asm volatile("cp.async.wait_group 1;\n"  ::: "memory")
#define CP_WAIT0()  asm volatile("cp.async.wait_group 0;\n"  ::: "memory")

// ---------------------------------------------------------------------------
// prep: split fp32 -> bf16 hi/lo
// ---------------------------------------------------------------------------
__global__ void split_f32(const float* __restrict__ src,
                          __nv_bfloat16* __restrict__ hi,
                          __nv_bfloat16* __restrict__ lo, int n)
{
    int i = blockIdx.x * blockDim.x + threadIdx.x;
    if (i < n) {
        float x = src[i];
        __nv_bfloat16 h = __float2bfloat16_rn(x);
        hi[i] = h;
        lo[i] = __float2bfloat16_rn(x - __bfloat162float(h));
    }
}

// ---------------------------------------------------------------------------
// split-2 bf16 GEMM:  C = A @ B^T.  A:[M,K] rm hi/lo, B:[N,K] rm hi/lo.
// Block 128x128, kTile 32 (bf16), 256 threads (8 warps, warp tile 32x64).
// 3-stage cp.async pipeline. Inner loop: LDS + 3 bf16 mma per (mt,nt).
// MODE 0: fp32 store C.  MODE 1: QKV split/scatter epilogue.
// ---------------------------------------------------------------------------
#define GST    20                          // smem row stride in u32 (16 data + 4 pad)
#define GCOMP  (128 * GST)                 // u32 per component per stage
#define GSTAGE (4 * GCOMP)                 // Ah, Al, Bh, Bl
#define GEMM_SMEM (3 * GSTAGE * 4)         // 122880 bytes

template <int MODE>
__global__ void __launch_bounds__(256)
gemm_bf2(const __nv_bfloat16* __restrict__ Ah, const __nv_bfloat16* __restrict__ Al,
         const __nv_bfloat16* __restrict__ Bh, const __nv_bfloat16* __restrict__ Bl,
         float* __restrict__ C, int K, int N)
{
    extern __shared__ uint32_t smu[];

    const int tid  = threadIdx.x;
    const int lane = tid & 31;
    const int w    = tid >> 5;
    const int gr   = lane >> 2;
    const int tig  = lane & 3;
    const int wm   = w & 3;              // 32-row quadrant
    const int wn   = w >> 2;             // 64-col half

    const int row0 = blockIdx.y * 128;
    const int col0 = blockIdx.x * 128;

    float acc[2][8][4];
#pragma unroll
    for (int i = 0; i < 2; i++)
#pragma unroll
        for (int j = 0; j < 8; j++)
#pragma unroll
            for (int e = 0; e < 4; e++) acc[i][j][e] = 0.f;

    // stage loader: per component 128 rows x 32 bf16 (4 x 16B chunks per row)
    auto loadTile = [&](int s, int kt) {
        uint32_t* st = smu + (size_t)s * GSTAGE;
#pragma unroll
        for (int p = 0; p < 2; p++) {
            int c   = tid + 256 * p;         // 0..511
            int row = c >> 2;
            int ch  = c & 3;
            uint32_t* d0 = st + row * GST + ch * 4;
            size_t ga = (size_t)(row0 + row) * K + kt + ch * 8;
            size_t gb = (size_t)(col0 + row) * K + kt + ch * 8;
            cpasync16(d0,                 Ah + ga);
            cpasync16(d0 + GCOMP,         Al + ga);
            cpasync16(d0 + 2 * GCOMP,     Bh + gb);
            cpasync16(d0 + 3 * GCOMP,     Bl + gb);
        }
    };

    const int nk = K / 32;
    loadTile(0, 0);  CP_COMMIT();
    loadTile(1, 32); CP_COMMIT();

    for (int t = 0; t < nk; t++) {
        const int s = t % 3;
        if (t == nk - 1) { CP_WAIT0(); } else { CP_WAIT1(); }
        __syncthreads();

        const uint32_t* ash = smu + (size_t)s * GSTAGE;
        const uint32_t* asl = ash + GCOMP;
        const uint32_t* bsh = ash + 2 * GCOMP;
        const uint32_t* bsl = ash + 3 * GCOMP;

#pragma unroll
        for (int ks = 0; ks < 2; ks++) {
            const int base = ks * 8;
            uint32_t ah[2][4], al_[2][4];
#pragma unroll
            for (int mt = 0; mt < 2; mt++) {
                int r = wm * 32 + mt * 16 + gr;
                ah[mt][0]  = ash[(r    ) * GST + base + tig];
                ah[mt][1]  = ash[(r + 8) * GST + base + tig];
                ah[mt][2]  = ash[(r    ) * GST + base + tig + 4];
                ah[mt][3]  = ash[(r + 8) * GST + base + tig + 4];
                al_[mt][0] = asl[(r    ) * GST + base + tig];
                al_[mt][1] = asl[(r + 8) * GST + base + tig];
                al_[mt][2] = asl[(r    ) * GST + base + tig + 4];
                al_[mt][3] = asl[(r + 8) * GST + base + tig + 4];
            }
            uint32_t bh[8][2], bl[8][2];
#pragma unroll
            for (int nt = 0; nt < 8; nt++) {
                int cn = wn * 64 + nt * 8 + gr;
                bh[nt][0] = bsh[cn * GST + base + tig];
                bh[nt][1] = bsh[cn * GST + base + tig + 4];
                bl[nt][0] = bsl[cn * GST + base + tig];
                bl[nt][1] = bsl[cn * GST + base + tig + 4];
            }
#pragma unroll
            for (int mt = 0; mt < 2; mt++)
#pragma unroll
                for (int nt = 0; nt < 8; nt++) {
                    mma_bf16(acc[mt][nt], ah[mt],  bh[nt]);
                    mma_bf16(acc[mt][nt], ah[mt],  bl[nt]);
                    mma_bf16(acc[mt][nt], al_[mt], bh[nt]);
                }
        }
        __syncthreads();
        if (t + 2 < nk) { loadTile((t + 2) % 3, (t + 2) * 32); CP_COMMIT(); }
    }

    // ---- epilogue
#pragma unroll
    for (int mt = 0; mt < 2; mt++) {
#pragma unroll
        for (int e2 = 0; e2 < 2; e2++) {
            int r = row0 + wm * 32 + mt * 16 + gr + e2 * 8;
#pragma unroll
            for (int nt = 0; nt < 8; nt++) {
                int n = col0 + wn * 64 + nt * 8 + 2 * tig;
                float v0 = acc[mt][nt][e2 * 2 + 0];
                float v1 = acc[mt][nt][e2 * 2 + 1];
                if (MODE == 0) {
                    *(float2*)&C[(size_t)r * N + n] = make_float2(v0, v1);
                } else {
                    int b   = r >> 11;            // / SEQ
                    int tk  = r & (SEQ - 1);
                    int sec = n >> 10;
                    int c   = n & 1023;
                    int h   = c >> 6;
                    int d   = c & 63;
                    int bh_ = b * NHEAD + h;
                    if (sec == 2) {
                        // V: store transposed [B,H,D,T], scalar bf16
                        size_t i0 = ((size_t)bh_ * HDIM + d) * SEQ + tk;
                        __nv_bfloat16 h0 = __float2bfloat16_rn(v0);
                        __nv_bfloat16 h1 = __float2bfloat16_rn(v1);
                        g_vth[i0]       = h0;
                        g_vth[i0 + SEQ] = h1;
                        g_vtl[i0]       = __float2bfloat16_rn(v0 - __bfloat162float(h0));
                        g_vtl[i0 + SEQ] = __float2bfloat16_rn(v1 - __bfloat162float(h1));
                    } else {
                        uint32_t hp, lp;
                        splitpack(v0, v1, hp, lp);
                        size_t i2 = (((size_t)bh_ * SEQ + tk) * HDIM + d) >> 1;  // u32 idx
                        if (sec == 0) {
                            ((uint32_t*)g_qh)[i2] = hp;
                            ((uint32_t*)g_ql)[i2] = lp;
                        } else {
                            ((uint32_t*)g_kh)[i2] = hp;
                            ((uint32_t*)g_kl)[i2] = lp;
                        }
                    }
                }
            }
        }
    }
}

// ---------------------------------------------------------------------------
// Causal flash attention, split-2 bf16 mma. Br=128, Bc=64, D=64.
// 256 threads = 8 warps; warp w owns q rows [16w, 16w+16).
// grid: (SEQ/128, B*H)
// ---------------------------------------------------------------------------
#define AST 36                                   // smem row stride in u32
#define ATT_SMEM ((2 * 128 + 4 * 64) * AST * 4)  // 73728 bytes

__global__ void __launch_bounds__(256)
attn_bf2()
{
    extern __shared__ uint32_t smu[];
    uint32_t* QPh = smu;                    // [128][AST]  Q hi, reused for P hi
    uint32_t* QPl = QPh + 128 * AST;        // [128][AST]  Q lo, reused for P lo
    uint32_t* Ksh = QPl + 128 * AST;        // [64][AST]
    uint32_t* Ksl = Ksh + 64 * AST;
    uint32_t* Vth = Ksl + 64 * AST;         // [64][AST]  V transposed [d][t]
    uint32_t* Vtl = Vth + 64 * AST;

    const int tid  = threadIdx.x;
    const int lane = tid & 31;
    const int w    = tid >> 5;
    const int gr   = lane >> 2;
    const int tig  = lane & 3;
    const int m0   = w * 16;

    const int qb = blockIdx.x;
    const int bh = blockIdx.y;
    const int b  = bh >> 4;
    const int h  = bh & 15;
    const int q0 = qb * 128;

    const size_t bhoff = (size_t)bh * SEQ * HDIM;

    // ---- load Q tile (hi/lo) into smem
    {
        const uint4* qh4 = (const uint4*)(g_qh + bhoff + (size_t)q0 * HDIM);
        const uint4* ql4 = (const uint4*)(g_ql + bhoff + (size_t)q0 * HDIM);
        for (int i = tid; i < 128 * 8; i += 256) {
            int row = i >> 3, ch = i & 7;
            *(uint4*)&QPh[row * AST + ch * 4] = qh4[row * 8 + ch];
            *(uint4*)&QPl[row * AST + ch * 4] = ql4[row * 8 + ch];
        }
    }
    __syncthreads();

    // ---- build persistent Q fragments
    uint32_t qfh[4][4], qfl[4][4];
#pragma unroll
    for (int dk = 0; dk < 4; dk++) {
        qfh[dk][0] = QPh[(m0 + gr    ) * AST + dk * 8 + tig];
        qfh[dk][1] = QPh[(m0 + gr + 8) * AST + dk * 8 + tig];
        qfh[dk][2] = QPh[(m0 + gr    ) * AST + dk * 8 + tig + 4];
        qfh[dk][3] = QPh[(m0 + gr + 8) * AST + dk * 8 + tig + 4];
        qfl[dk][0] = QPl[(m0 + gr    ) * AST + dk * 8 + tig];
        qfl[dk][1] = QPl[(m0 + gr + 8) * AST + dk * 8 + tig];
        qfl[dk][2] = QPl[(m0 + gr    ) * AST + dk * 8 + tig + 4];
        qfl[dk][3] = QPl[(m0 + gr + 8) * AST + dk * 8 + tig + 4];
    }
    __syncthreads();   // QP now free for P

    float o[8][4];
#pragma unroll
    for (int nt = 0; nt < 8; nt++)
#pragma unroll
        for (int e = 0; e < 4; e++) o[nt][e] = 0.f;
    float mrow[2] = {-1e30f, -1e30f};
    float lrow[2] = {0.f, 0.f};

    const int ktmax = 2 * qb + 1;
    for (int kt = 0; kt <= ktmax; kt++) {
        __syncthreads();     // protect Ks/Vt/QP(P) from previous iteration
        const int k0 = kt * 64;
        {
            const uint4* kh4 = (const uint4*)(g_kh + bhoff + (size_t)k0 * HDIM);
            const uint4* kl4 = (const uint4*)(g_kl + bhoff + (size_t)k0 * HDIM);
            const uint4* vh4 = (const uint4*)(g_vth + (size_t)bh * HDIM * SEQ + k0);
            const uint4* vl4 = (const uint4*)(g_vtl + (size_t)bh * HDIM * SEQ + k0);
            for (int i = tid; i < 64 * 8; i += 256) {
                int row = i >> 3, ch = i & 7;
                *(uint4*)&Ksh[row * AST + ch * 4] = kh4[row * 8 + ch];
                *(uint4*)&Ksl[row * AST + ch * 4] = kl4[row * 8 + ch];
                // V transposed rows are d; global row stride = SEQ bf16 = 256 uint4
                *(uint4*)&Vth[row * AST + ch * 4] = vh4[row * 256 + ch];
                *(uint4*)&Vtl[row * AST + ch * 4] = vl4[row * 256 + ch];
            }
        }
        __syncthreads();

        // ---- S = Q K^T (split-2)
        float sfr[8][4];
#pragma unroll
        for (int nt = 0; nt < 8; nt++)
#pragma unroll
            for (int e = 0; e < 4; e++) sfr[nt][e] = 0.f;

#pragma unroll
        for (int dk = 0; dk < 4; dk++) {
            uint32_t kfh[8][2], kfl[8][2];
#pragma unroll
            for (int nt = 0; nt < 8; nt++) {
                int kn = nt * 8 + gr;
                kfh[nt][0] = Ksh[kn * AST + dk * 8 + tig];
                kfh[nt][1] = Ksh[kn * AST + dk * 8 + tig + 4];
                kfl[nt][0] = Ksl[kn * AST + dk * 8 + tig];
                kfl[nt][1] = Ksl[kn * AST + dk * 8 + tig + 4];
            }
#pragma unroll
            for (int nt = 0; nt < 8; nt++) {
                mma_bf16(sfr[nt], qfh[dk], kfh[nt]);
                mma_bf16(sfr[nt], qfh[dk], kfl[nt]);
                mma_bf16(sfr[nt], qfl[dk], kfh[nt]);
            }
        }
        // scale 1/sqrt(D)
#pragma unroll
        for (int nt = 0; nt < 8; nt++)
#pragma unroll
            for (int e = 0; e < 4; e++) sfr[nt][e] *= 0.125f;

        // ---- causal mask (only near the diagonal)
        if (k0 + 63 > q0 + m0) {
#pragma unroll
            for (int nt = 0; nt < 8; nt++)
#pragma unroll
                for (int e = 0; e < 4; e++) {
                    int rg = q0 + m0 + gr + (e >> 1) * 8;
                    int cg = k0 + nt * 8 + 2 * tig + (e & 1);
                    if (cg > rg) sfr[nt][e] = -1e30f;
                }
        }

        // ---- online softmax (thread rows: gr, gr+8)
        float mx0 = -1e30f, mx1 = -1e30f;
#pragma unroll
        for (int nt = 0; nt < 8; nt++) {
            mx0 = fmaxf(mx0, fmaxf(sfr[nt][0], sfr[nt][1]));
            mx1 = fmaxf(mx1, fmaxf(sfr[nt][2], sfr[nt][3]));
        }
        mx0 = fmaxf(mx0, __shfl_xor_sync(0xffffffffu, mx0, 1));
        mx0 = fmaxf(mx0, __shfl_xor_sync(0xffffffffu, mx0, 2));
        mx1 = fmaxf(mx1, __shfl_xor_sync(0xffffffffu, mx1, 1));
        mx1 = fmaxf(mx1, __shfl_xor_sync(0xffffffffu, mx1, 2));

        float nm0 = fmaxf(mrow[0], mx0);
        float nm1 = fmaxf(mrow[1], mx1);
        float f0  = __expf(mrow[0] - nm0);
        float f1  = __expf(mrow[1] - nm1);

        float ps0 = 0.f, ps1 = 0.f;
#pragma unroll
        for (int nt = 0; nt < 8; nt++) {
            float p0 = __expf(sfr[nt][0] - nm0);
            float p1 = __expf(sfr[nt][1] - nm0);
            float p2 = __expf(sfr[nt][2] - nm1);
            float p3 = __expf(sfr[nt][3] - nm1);
            ps0 += p0 + p1;
            ps1 += p2 + p3;
            uint32_t hp, lp;
            splitpack(p0, p1, hp, lp);
            QPh[(m0 + gr) * AST + nt * 4 + tig] = hp;
            QPl[(m0 + gr) * AST + nt * 4 + tig] = lp;
            splitpack(p2, p3, hp, lp);
            QPh[(m0 + gr + 8) * AST + nt * 4 + tig] = hp;
            QPl[(m0 + gr + 8) * AST + nt * 4 + tig] = lp;
        }
        ps0 += __shfl_xor_sync(0xffffffffu, ps0, 1);
        ps0 += __shfl_xor_sync(0xffffffffu, ps0, 2);
        ps1 += __shfl_xor_sync(0xffffffffu, ps1, 1);
        ps1 += __shfl_xor_sync(0xffffffffu, ps1, 2);

        lrow[0] = lrow[0] * f0 + ps0;
        lrow[1] = lrow[1] * f1 + ps1;
        mrow[0] = nm0;
        mrow[1] = nm1;
#pragma unroll
        for (int nt = 0; nt < 8; nt++) {
            o[nt][0] *= f0; o[nt][1] *= f0;
            o[nt][2] *= f1; o[nt][3] *= f1;
        }
        __syncwarp();    // P is per-warp rows only

        // ---- O += P V (split-2)
#pragma unroll
        for (int kk = 0; kk < 4; kk++) {
            uint32_t pfh[4], pfl[4];
            pfh[0] = QPh[(m0 + gr    ) * AST + kk * 8 + tig];
            pfh[1] = QPh[(m0 + gr + 8) * AST + kk * 8 + tig];
            pfh[2] = QPh[(m0 + gr    ) * AST + kk * 8 + tig + 4];
            pfh[3] = QPh[(m0 + gr + 8) * AST + kk * 8 + tig + 4];
            pfl[0] = QPl[(m0 + gr    ) * AST + kk * 8 + tig];
            pfl[1] = QPl[(m0 + gr + 8) * AST + kk * 8 + tig];
            pfl[2] = QPl[(m0 + gr    ) * AST + kk * 8 + tig + 4];
            pfl[3] = QPl[(m0 + gr + 8) * AST + kk * 8 + tig + 4];
            uint32_t vfh[8][2], vfl[8][2];
#pragma unroll
            for (int nt = 0; nt < 8; nt++) {
                int dn = nt * 8 + gr;
                vfh[nt][0] = Vth[dn * AST + kk * 8 + tig];
                vfh[nt][1] = Vth[dn * AST + kk * 8 + tig + 4];
                vfl[nt][0] = Vtl[dn * AST + kk * 8 + tig];
                vfl[nt][1] = Vtl[dn * AST + kk * 8 + tig + 4];
            }
#pragma unroll
            for (int nt = 0; nt < 8; nt++) {
                mma_bf16(o[nt], pfh, vfh[nt]);
                mma_bf16(o[nt], pfh, vfl[nt]);
                mma_bf16(o[nt], pfl, vfh[nt]);
            }
        }
    }

    // ---- normalize, split, store to g_ao (bf16 hi/lo, [B*T, C])
    float inv0 = 1.0f / lrow[0];
    float inv1 = 1.0f / lrow[1];
    int r0 = q0 + m0 + gr;
    uint32_t* aoh = (uint32_t*)g_aoh;
    uint32_t* aol = (uint32_t*)g_aol;
#pragma unroll
    for (int nt = 0; nt < 8; nt++) {
        size_t cu = (size_t)h * 32 + nt * 4 + tig;   // u32 col
        uint32_t hp, lp;
        splitpack(o[nt][0] * inv0, o[nt][1] * inv0, hp, lp);
        aoh[(size_t)(b * SEQ + r0) * (EMBED / 2) + cu] = hp;
        aol[(size_t)(b * SEQ + r0) * (EMBED / 2) + cu] = lp;
        splitpack(o[nt][2] * inv1, o[nt][3] * inv1, hp, lp);
        aoh[(size_t)(b * SEQ + r0 + 8) * (EMBED / 2) + cu] = hp;
        aol[(size_t)(b * SEQ + r0 + 8) * (EMBED / 2) + cu] = lp;
    }
}

// ---------------------------------------------------------------------------
extern "C" void kernel_launch(void* const* d_in, const int* in_sizes, int n_in,
                              void* d_out, int out_size)
{
    const float* x      = (const float*)d_in[0];   // [4,2048,1024]
    const float* W_qkv  = (const float*)d_in[1];   // [3072,1024]
    const float* W_proj = (const float*)d_in[2];   // [1024,1024]
    float* out = (float*)d_out;                    // [4,2048,1024]

    __nv_bfloat16 *xh, *xl, *wqh, *wql, *wph, *wpl, *aoh, *aol;
    cudaGetSymbolAddress((void**)&xh,  g_xh);
    cudaGetSymbolAddress((void**)&xl,  g_xl);
    cudaGetSymbolAddress((void**)&wqh, g_wqh);
    cudaGetSymbolAddress((void**)&wql, g_wql);
    cudaGetSymbolAddress((void**)&wph, g_wph);
    cudaGetSymbolAddress((void**)&wpl, g_wpl);
    cudaGetSymbolAddress((void**)&aoh, g_aoh);
    cudaGetSymbolAddress((void**)&aol, g_aol);

    // 0) split inputs into bf16 hi/lo
    split_f32<<<(MROWS * EMBED + 255) / 256, 256>>>(x, xh, xl, MROWS * EMBED);
    split_f32<<<(3 * EMBED * EMBED + 255) / 256, 256>>>(W_qkv, wqh, wql, 3 * EMBED * EMBED);
    split_f32<<<(EMBED * EMBED + 255) / 256, 256>>>(W_proj, wph, wpl, EMBED * EMBED);

    // 1) QKV projection with split/scatter epilogue
    {
        cudaFuncSetAttribute((const void*)gemm_bf2<1>,
                             cudaFuncAttributeMaxDynamicSharedMemorySize, GEMM_SMEM);
        dim3 grid(3 * EMBED / 128, MROWS / 128);
        gemm_bf2<1><<<grid, 256, GEMM_SMEM>>>(xh, xl, wqh, wql, nullptr, EMBED, 3 * EMBED);
    }

    // 2) causal flash attention -> g_ao (split bf16)
    {
        cudaFuncSetAttribute((const void*)attn_bf2,
                             cudaFuncAttributeMaxDynamicSharedMemorySize, ATT_SMEM);
        dim3 grid(SEQ / 128, BATCH * NHEAD);
        attn_bf2<<<grid, 256, ATT_SMEM>>>();
    }

    // 3) output projection -> d_out (fp32)
    {
        cudaFuncSetAttribute((const void*)gemm_bf2<0>,
                             cudaFuncAttributeMaxDynamicSharedMemorySize, GEMM_SMEM);
        dim3 grid(EMBED / 128, MROWS / 128);
        gemm_bf2<0><<<grid, 256, GEMM_SMEM>>>(aoh, aol, wph, wpl, out, EMBED, EMBED);
    }
}

// round 5
// speedup vs baseline: 5.4206x; 1.2473x over previous
#include <cuda_runtime.h>
#include <cuda_bf16.h>
#include <cstdint>

// Problem constants
#define EMBED   1024
#define NHEAD   16
#define HDIM    64
#define BATCH   4
#define SEQ     2048
#define MROWS   (BATCH * SEQ)                 // 8192
#define QKVN    (BATCH * NHEAD * SEQ * HDIM)  // 8388608

// ---------------------------------------------------------------------------
// Persistent scratch (bf16 hi/lo split everywhere)
// ---------------------------------------------------------------------------
__device__ __align__(16) __nv_bfloat16 g_xh [MROWS * EMBED];
__device__ __align__(16) __nv_bfloat16 g_xl [MROWS * EMBED];
__device__ __align__(16) __nv_bfloat16 g_wqh[3 * EMBED * EMBED];
__device__ __align__(16) __nv_bfloat16 g_wql[3 * EMBED * EMBED];
__device__ __align__(16) __nv_bfloat16 g_wph[EMBED * EMBED];
__device__ __align__(16) __nv_bfloat16 g_wpl[EMBED * EMBED];
__device__ __align__(16) __nv_bfloat16 g_qh [QKVN];   // [B,H,T,D]
__device__ __align__(16) __nv_bfloat16 g_ql [QKVN];
__device__ __align__(16) __nv_bfloat16 g_kh [QKVN];   // [B,H,T,D]
__device__ __align__(16) __nv_bfloat16 g_kl [QKVN];
__device__ __align__(16) __nv_bfloat16 g_vth[QKVN];   // [B,H,D,T]  (transposed)
__device__ __align__(16) __nv_bfloat16 g_vtl[QKVN];
__device__ __align__(16) __nv_bfloat16 g_aoh[MROWS * EMBED];   // [B*T, C]
__device__ __align__(16) __nv_bfloat16 g_aol[MROWS * EMBED];

// ---------------------------------------------------------------------------
// helpers
// ---------------------------------------------------------------------------
__device__ __forceinline__ void mma_bf16(float* c, const uint32_t* a, const uint32_t* b) {
    asm volatile(
        "mma.sync.aligned.m16n8k16.row.col.f32.bf16.bf16.f32 "
        "{%0,%1,%2,%3}, {%4,%5,%6,%7}, {%8,%9}, {%0,%1,%2,%3};"
        : "+f"(c[0]), "+f"(c[1]), "+f"(c[2]), "+f"(c[3])
        : "r"(a[0]), "r"(a[1]), "r"(a[2]), "r"(a[3]), "r"(b[0]), "r"(b[1]));
}
__device__ __forceinline__ void splitpack(float x0, float x1, uint32_t& hp, uint32_t& lp) {
    __nv_bfloat16 h0 = __float2bfloat16_rn(x0);
    __nv_bfloat16 h1 = __float2bfloat16_rn(x1);
    __nv_bfloat16 l0 = __float2bfloat16_rn(x0 - __bfloat162float(h0));
    __nv_bfloat16 l1 = __float2bfloat16_rn(x1 - __bfloat162float(h1));
    hp = (uint32_t)__bfloat16_as_ushort(h0) | ((uint32_t)__bfloat16_as_ushort(h1) << 16);
    lp = (uint32_t)__bfloat16_as_ushort(l0) | ((uint32_t)__bfloat16_as_ushort(l1) << 16);
}
__device__ __forceinline__ void cpasync16(void* s, const void* g) {
    uint32_t sa = (uint32_t)__cvta_generic_to_shared(s);
    asm volatile("cp.async.cg.shared.global [%0], [%1], 16;\n" :: "r"(sa), "l"(g));
}
#define CP_COMMIT() asm volatile("cp.async.commit_group;\n" ::: "memory")
#define CP_WAIT1()  asm volatile("cp.async.wait_group 1;\n"  ::: "memory")
#define CP_WAIT0()  asm volatile("cp.async.wait_group 0;\n"  ::: "memory")

// ---------------------------------------------------------------------------
// prep: split fp32 -> bf16 hi/lo (vectorized, 4 elems/thread)
// ---------------------------------------------------------------------------
__global__ void split_f32(const float4* __restrict__ src,
                          uint2* __restrict__ hi,
                          uint2* __restrict__ lo, int n4)
{
    int i = blockIdx.x * blockDim.x + threadIdx.x;
    if (i < n4) {
        float4 v = src[i];
        uint32_t h0, l0, h1, l1;
        splitpack(v.x, v.y, h0, l0);
        splitpack(v.z, v.w, h1, l1);
        hi[i] = make_uint2(h0, h1);
        lo[i] = make_uint2(l0, l1);
    }
}

// ---------------------------------------------------------------------------
// split-2 bf16 GEMM:  C = A @ B^T.  A:[M,K] rm hi/lo, B:[N,K] rm hi/lo.
// Block 128x128, kTile 32 (bf16), 256 threads (8 warps, warp tile 32x64).
// 2-stage cp.async pipeline (80KB smem -> 2 CTAs/SM).
// MODE 0: fp32 store C.  MODE 1: QKV split/scatter epilogue.
// ---------------------------------------------------------------------------
#define GST    20                          // smem row stride in u32 (16 data + 4 pad)
#define GCOMP  (128 * GST)                 // u32 per component per stage
#define GSTAGE (4 * GCOMP)                 // Ah, Al, Bh, Bl
#define GEMM_SMEM (2 * GSTAGE * 4)         // 81920 bytes

template <int MODE>
__global__ void __launch_bounds__(256, 2)
gemm_bf2(const __nv_bfloat16* __restrict__ Ah, const __nv_bfloat16* __restrict__ Al,
         const __nv_bfloat16* __restrict__ Bh, const __nv_bfloat16* __restrict__ Bl,
         float* __restrict__ C, int K, int N)
{
    extern __shared__ uint32_t smu[];

    const int tid  = threadIdx.x;
    const int lane = tid & 31;
    const int w    = tid >> 5;
    const int gr   = lane >> 2;
    const int tig  = lane & 3;
    const int wm   = w & 3;              // 32-row quadrant
    const int wn   = w >> 2;             // 64-col half

    const int row0 = blockIdx.y * 128;
    const int col0 = blockIdx.x * 128;

    float acc[2][8][4];
#pragma unroll
    for (int i = 0; i < 2; i++)
#pragma unroll
        for (int j = 0; j < 8; j++)
#pragma unroll
            for (int e = 0; e < 4; e++) acc[i][j][e] = 0.f;

    // stage loader: per component 128 rows x 32 bf16 (4 x 16B chunks per row)
    auto loadTile = [&](int s, int kt) {
        uint32_t* st = smu + (size_t)s * GSTAGE;
#pragma unroll
        for (int p = 0; p < 2; p++) {
            int c   = tid + 256 * p;         // 0..511
            int row = c >> 2;
            int ch  = c & 3;
            uint32_t* d0 = st + row * GST + ch * 4;
            size_t ga = (size_t)(row0 + row) * K + kt + ch * 8;
            size_t gb = (size_t)(col0 + row) * K + kt + ch * 8;
            cpasync16(d0,                 Ah + ga);
            cpasync16(d0 + GCOMP,         Al + ga);
            cpasync16(d0 + 2 * GCOMP,     Bh + gb);
            cpasync16(d0 + 3 * GCOMP,     Bl + gb);
        }
    };

    const int nk = K / 32;
    loadTile(0, 0);  CP_COMMIT();
    loadTile(1, 32); CP_COMMIT();

    for (int t = 0; t < nk; t++) {
        const int s = t & 1;
        if (t >= nk - 2) { CP_WAIT0(); } else { CP_WAIT1(); }
        __syncthreads();

        const uint32_t* ash = smu + (size_t)s * GSTAGE;
        const uint32_t* asl = ash + GCOMP;
        const uint32_t* bsh = ash + 2 * GCOMP;
        const uint32_t* bsl = ash + 3 * GCOMP;

#pragma unroll
        for (int ks = 0; ks < 2; ks++) {
            const int base = ks * 8;
            uint32_t ah[2][4], al_[2][4];
#pragma unroll
            for (int mt = 0; mt < 2; mt++) {
                int r = wm * 32 + mt * 16 + gr;
                ah[mt][0]  = ash[(r    ) * GST + base + tig];
                ah[mt][1]  = ash[(r + 8) * GST + base + tig];
                ah[mt][2]  = ash[(r    ) * GST + base + tig + 4];
                ah[mt][3]  = ash[(r + 8) * GST + base + tig + 4];
                al_[mt][0] = asl[(r    ) * GST + base + tig];
                al_[mt][1] = asl[(r + 8) * GST + base + tig];
                al_[mt][2] = asl[(r    ) * GST + base + tig + 4];
                al_[mt][3] = asl[(r + 8) * GST + base + tig + 4];
            }
            uint32_t bh[8][2], bl[8][2];
#pragma unroll
            for (int nt = 0; nt < 8; nt++) {
                int cn = wn * 64 + nt * 8 + gr;
                bh[nt][0] = bsh[cn * GST + base + tig];
                bh[nt][1] = bsh[cn * GST + base + tig + 4];
                bl[nt][0] = bsl[cn * GST + base + tig];
                bl[nt][1] = bsl[cn * GST + base + tig + 4];
            }
#pragma unroll
            for (int mt = 0; mt < 2; mt++)
#pragma unroll
                for (int nt = 0; nt < 8; nt++) {
                    mma_bf16(acc[mt][nt], ah[mt],  bh[nt]);
                    mma_bf16(acc[mt][nt], ah[mt],  bl[nt]);
                    mma_bf16(acc[mt][nt], al_[mt], bh[nt]);
                }
        }
        __syncthreads();
        if (t + 2 < nk) { loadTile(s, (t + 2) * 32); CP_COMMIT(); }
    }

    // ---- epilogue
#pragma unroll
    for (int mt = 0; mt < 2; mt++) {
#pragma unroll
        for (int e2 = 0; e2 < 2; e2++) {
            int r = row0 + wm * 32 + mt * 16 + gr + e2 * 8;
#pragma unroll
            for (int nt = 0; nt < 8; nt++) {
                int n = col0 + wn * 64 + nt * 8 + 2 * tig;
                float v0 = acc[mt][nt][e2 * 2 + 0];
                float v1 = acc[mt][nt][e2 * 2 + 1];
                if (MODE == 0) {
                    *(float2*)&C[(size_t)r * N + n] = make_float2(v0, v1);
                } else {
                    int b   = r >> 11;            // / SEQ
                    int tk  = r & (SEQ - 1);
                    int sec = n >> 10;
                    int c   = n & 1023;
                    int h   = c >> 6;
                    int d   = c & 63;
                    int bh_ = b * NHEAD + h;
                    if (sec == 2) {
                        // V: store transposed [B,H,D,T], scalar bf16
                        size_t i0 = ((size_t)bh_ * HDIM + d) * SEQ + tk;
                        __nv_bfloat16 h0 = __float2bfloat16_rn(v0);
                        __nv_bfloat16 h1 = __float2bfloat16_rn(v1);
                        g_vth[i0]       = h0;
                        g_vth[i0 + SEQ] = h1;
                        g_vtl[i0]       = __float2bfloat16_rn(v0 - __bfloat162float(h0));
                        g_vtl[i0 + SEQ] = __float2bfloat16_rn(v1 - __bfloat162float(h1));
                    } else {
                        uint32_t hp, lp;
                        splitpack(v0, v1, hp, lp);
                        size_t i2 = (((size_t)bh_ * SEQ + tk) * HDIM + d) >> 1;  // u32 idx
                        if (sec == 0) {
                            ((uint32_t*)g_qh)[i2] = hp;
                            ((uint32_t*)g_ql)[i2] = lp;
                        } else {
                            ((uint32_t*)g_kh)[i2] = hp;
                            ((uint32_t*)g_kl)[i2] = lp;
                        }
                    }
                }
            }
        }
    }
}

// ---------------------------------------------------------------------------
// Causal flash attention, split-2 bf16 mma.sync. Br=128, Bc=64, D=64.
// 256 threads = 8 warps; warp w owns q rows [16w, 16w+16).
// 2-stage cp.async prefetch of K/V (hi/lo). Q pre-scaled by 0.125 in bf16.
// grid: (SEQ/128, B*H)
// ---------------------------------------------------------------------------
#define AST 36                                   // smem row stride in u32
#define ATT_QP_U32  (2 * 128 * AST)              // QPh + QPl
#define ATT_STG_U32 (4 * 64 * AST)               // Ksh, Ksl, Vth, Vtl per stage
#define ATT_SMEM ((ATT_QP_U32 + 2 * ATT_STG_U32) * 4)   // 110592 bytes

__global__ void __launch_bounds__(256, 2)
attn_bf2()
{
    extern __shared__ uint32_t smu[];
    uint32_t* QPh = smu;                    // [128][AST]  Q hi, reused for P hi
    uint32_t* QPl = QPh + 128 * AST;        // [128][AST]  Q lo, reused for P lo
    uint32_t* Stg = QPl + 128 * AST;        // 2 stages of K/V hi/lo

    const int tid  = threadIdx.x;
    const int lane = tid & 31;
    const int w    = tid >> 5;
    const int gr   = lane >> 2;
    const int tig  = lane & 3;
    const int m0   = w * 16;

    const int qb = blockIdx.x;
    const int bh = blockIdx.y;
    const int b  = bh >> 4;
    const int h  = bh & 15;
    const int q0 = qb * 128;

    const size_t bhoff = (size_t)bh * SEQ * HDIM;
    const size_t vtoff = (size_t)bh * HDIM * SEQ;

    // K/V prefetch (cp.async, 2 stages)
    auto loadKV = [&](int s, int kt) {
        const int k0 = kt * 64;
        uint32_t* st = Stg + s * ATT_STG_U32;
        for (int i = tid; i < 64 * 8; i += 256) {
            int row = i >> 3, ch = i & 7;
            uint32_t* d = st + row * AST + ch * 4;
            size_t gk = bhoff + (size_t)(k0 + row) * HDIM + ch * 8;
            size_t gv = vtoff + (size_t)row * SEQ + k0 + ch * 8;
            cpasync16(d,                g_kh  + gk);
            cpasync16(d +     64 * AST, g_kl  + gk);
            cpasync16(d + 2 * 64 * AST, g_vth + gv);
            cpasync16(d + 3 * 64 * AST, g_vtl + gv);
        }
    };

    const int ktmax = 2 * qb + 1;          // >= 1 always
    loadKV(0, 0); CP_COMMIT();
    loadKV(1, 1); CP_COMMIT();

    // ---- load Q tile (hi/lo) into smem, pre-scaled by 0.125 (exact in bf16)
    {
        const __nv_bfloat162 c2 = __floats2bfloat162_rn(0.125f, 0.125f);
        const uint4* qh4 = (const uint4*)(g_qh + bhoff + (size_t)q0 * HDIM);
        const uint4* ql4 = (const uint4*)(g_ql + bhoff + (size_t)q0 * HDIM);
        for (int i = tid; i < 128 * 8; i += 256) {
            int row = i >> 3, ch = i & 7;
            uint4 a = qh4[row * 8 + ch];
            __nv_bfloat162* ap = (__nv_bfloat162*)&a;
#pragma unroll
            for (int e = 0; e < 4; e++) ap[e] = __hmul2(ap[e], c2);
            *(uint4*)&QPh[row * AST + ch * 4] = a;
            uint4 bq = ql4[row * 8 + ch];
            __nv_bfloat162* bp = (__nv_bfloat162*)&bq;
#pragma unroll
            for (int e = 0; e < 4; e++) bp[e] = __hmul2(bp[e], c2);
            *(uint4*)&QPl[row * AST + ch * 4] = bq;
        }
    }
    __syncthreads();

    // ---- build persistent Q fragments
    uint32_t qfh[4][4], qfl[4][4];
#pragma unroll
    for (int dk = 0; dk < 4; dk++) {
        qfh[dk][0] = QPh[(m0 + gr    ) * AST + dk * 8 + tig];
        qfh[dk][1] = QPh[(m0 + gr + 8) * AST + dk * 8 + tig];
        qfh[dk][2] = QPh[(m0 + gr    ) * AST + dk * 8 + tig + 4];
        qfh[dk][3] = QPh[(m0 + gr + 8) * AST + dk * 8 + tig + 4];
        qfl[dk][0] = QPl[(m0 + gr    ) * AST + dk * 8 + tig];
        qfl[dk][1] = QPl[(m0 + gr + 8) * AST + dk * 8 + tig];
        qfl[dk][2] = QPl[(m0 + gr    ) * AST + dk * 8 + tig + 4];
        qfl[dk][3] = QPl[(m0 + gr + 8) * AST + dk * 8 + tig + 4];
    }
    __syncthreads();   // QP now free for P

    float o[8][4];
#pragma unroll
    for (int nt = 0; nt < 8; nt++)
#pragma unroll
        for (int e = 0; e < 4; e++) o[nt][e] = 0.f;
    float mrow[2] = {-1e30f, -1e30f};
    float lrow[2] = {0.f, 0.f};

    for (int kt = 0; kt <= ktmax; kt++) {
        const int s = kt & 1;
        if (kt == ktmax) { CP_WAIT0(); } else { CP_WAIT1(); }
        __syncthreads();

        const uint32_t* Ksh = Stg + s * ATT_STG_U32;
        const uint32_t* Ksl = Ksh + 64 * AST;
        const uint32_t* Vth = Ksh + 2 * 64 * AST;
        const uint32_t* Vtl = Ksh + 3 * 64 * AST;
        const int k0 = kt * 64;

        // ---- S = Q K^T (split-2)
        float sfr[8][4];
#pragma unroll
        for (int nt = 0; nt < 8; nt++)
#pragma unroll
            for (int e = 0; e < 4; e++) sfr[nt][e] = 0.f;

#pragma unroll
        for (int dk = 0; dk < 4; dk++) {
            uint32_t kfh[8][2], kfl[8][2];
#pragma unroll
            for (int nt = 0; nt < 8; nt++) {
                int kn = nt * 8 + gr;
                kfh[nt][0] = Ksh[kn * AST + dk * 8 + tig];
                kfh[nt][1] = Ksh[kn * AST + dk * 8 + tig + 4];
                kfl[nt][0] = Ksl[kn * AST + dk * 8 + tig];
                kfl[nt][1] = Ksl[kn * AST + dk * 8 + tig + 4];
            }
#pragma unroll
            for (int nt = 0; nt < 8; nt++) {
                mma_bf16(sfr[nt], qfh[dk], kfh[nt]);
                mma_bf16(sfr[nt], qfh[dk], kfl[nt]);
                mma_bf16(sfr[nt], qfl[dk], kfh[nt]);
            }
        }

        // ---- causal mask (only near the diagonal)
        if (k0 + 63 > q0 + m0) {
#pragma unroll
            for (int nt = 0; nt < 8; nt++)
#pragma unroll
                for (int e = 0; e < 4; e++) {
                    int rg = q0 + m0 + gr + (e >> 1) * 8;
                    int cg = k0 + nt * 8 + 2 * tig + (e & 1);
                    if (cg > rg) sfr[nt][e] = -1e30f;
                }
        }

        // ---- online softmax (thread rows: gr, gr+8)
        float mx0 = -1e30f, mx1 = -1e30f;
#pragma unroll
        for (int nt = 0; nt < 8; nt++) {
            mx0 = fmaxf(mx0, fmaxf(sfr[nt][0], sfr[nt][1]));
            mx1 = fmaxf(mx1, fmaxf(sfr[nt][2], sfr[nt][3]));
        }
        mx0 = fmaxf(mx0, __shfl_xor_sync(0xffffffffu, mx0, 1));
        mx0 = fmaxf(mx0, __shfl_xor_sync(0xffffffffu, mx0, 2));
        mx1 = fmaxf(mx1, __shfl_xor_sync(0xffffffffu, mx1, 1));
        mx1 = fmaxf(mx1, __shfl_xor_sync(0xffffffffu, mx1, 2));

        float nm0 = fmaxf(mrow[0], mx0);
        float nm1 = fmaxf(mrow[1], mx1);
        float f0  = __expf(mrow[0] - nm0);
        float f1  = __expf(mrow[1] - nm1);

        float ps0 = 0.f, ps1 = 0.f;
#pragma unroll
        for (int nt = 0; nt < 8; nt++) {
            float p0 = __expf(sfr[nt][0] - nm0);
            float p1 = __expf(sfr[nt][1] - nm0);
            float p2 = __expf(sfr[nt][2] - nm1);
            float p3 = __expf(sfr[nt][3] - nm1);
            ps0 += p0 + p1;
            ps1 += p2 + p3;
            uint32_t hp, lp;
            splitpack(p0, p1, hp, lp);
            QPh[(m0 + gr) * AST + nt * 4 + tig] = hp;
            QPl[(m0 + gr) * AST + nt * 4 + tig] = lp;
            splitpack(p2, p3, hp, lp);
            QPh[(m0 + gr + 8) * AST + nt * 4 + tig] = hp;
            QPl[(m0 + gr + 8) * AST + nt * 4 + tig] = lp;
        }
        ps0 += __shfl_xor_sync(0xffffffffu, ps0, 1);
        ps0 += __shfl_xor_sync(0xffffffffu, ps0, 2);
        ps1 += __shfl_xor_sync(0xffffffffu, ps1, 1);
        ps1 += __shfl_xor_sync(0xffffffffu, ps1, 2);

        lrow[0] = lrow[0] * f0 + ps0;
        lrow[1] = lrow[1] * f1 + ps1;
        mrow[0] = nm0;
        mrow[1] = nm1;
#pragma unroll
        for (int nt = 0; nt < 8; nt++) {
            o[nt][0] *= f0; o[nt][1] *= f0;
            o[nt][2] *= f1; o[nt][3] *= f1;
        }
        __syncwarp();    // P is per-warp rows only

        // ---- O += P V (split-2)
#pragma unroll
        for (int kk = 0; kk < 4; kk++) {
            uint32_t pfh[4], pfl[4];
            pfh[0] = QPh[(m0 + gr    ) * AST + kk * 8 + tig];
            pfh[1] = QPh[(m0 + gr + 8) * AST + kk * 8 + tig];
            pfh[2] = QPh[(m0 + gr    ) * AST + kk * 8 + tig + 4];
            pfh[3] = QPh[(m0 + gr + 8) * AST + kk * 8 + tig + 4];
            pfl[0] = QPl[(m0 + gr    ) * AST + kk * 8 + tig];
            pfl[1] = QPl[(m0 + gr + 8) * AST + kk * 8 + tig];
            pfl[2] = QPl[(m0 + gr    ) * AST + kk * 8 + tig + 4];
            pfl[3] = QPl[(m0 + gr + 8) * AST + kk * 8 + tig + 4];
            uint32_t vfh[8][2], vfl[8][2];
#pragma unroll
            for (int nt = 0; nt < 8; nt++) {
                int dn = nt * 8 + gr;
                vfh[nt][0] = Vth[dn * AST + kk * 8 + tig];
                vfh[nt][1] = Vth[dn * AST + kk * 8 + tig + 4];
                vfl[nt][0] = Vtl[dn * AST + kk * 8 + tig];
                vfl[nt][1] = Vtl[dn * AST + kk * 8 + tig + 4];
            }
#pragma unroll
            for (int nt = 0; nt < 8; nt++) {
                mma_bf16(o[nt], pfh, vfh[nt]);
                mma_bf16(o[nt], pfh, vfl[nt]);
                mma_bf16(o[nt], pfl, vfh[nt]);
            }
        }
        __syncthreads();     // all warps done with stage s
        if (kt + 2 <= ktmax) { loadKV(s, kt + 2); CP_COMMIT(); }
    }

    // ---- normalize, split, store to g_ao (bf16 hi/lo, [B*T, C])
    float inv0 = 1.0f / lrow[0];
    float inv1 = 1.0f / lrow[1];
    int r0 = q0 + m0 + gr;
    uint32_t* aoh = (uint32_t*)g_aoh;
    uint32_t* aol = (uint32_t*)g_aol;
#pragma unroll
    for (int nt = 0; nt < 8; nt++) {
        size_t cu = (size_t)h * 32 + nt * 4 + tig;   // u32 col
        uint32_t hp, lp;
        splitpack(o[nt][0] * inv0, o[nt][1] * inv0, hp, lp);
        aoh[(size_t)(b * SEQ + r0) * (EMBED / 2) + cu] = hp;
        aol[(size_t)(b * SEQ + r0) * (EMBED / 2) + cu] = lp;
        splitpack(o[nt][2] * inv1, o[nt][3] * inv1, hp, lp);
        aoh[(size_t)(b * SEQ + r0 + 8) * (EMBED / 2) + cu] = hp;
        aol[(size_t)(b * SEQ + r0 + 8) * (EMBED / 2) + cu] = lp;
    }
}

// ---------------------------------------------------------------------------
extern "C" void kernel_launch(void* const* d_in, const int* in_sizes, int n_in,
                              void* d_out, int out_size)
{
    const float* x      = (const float*)d_in[0];   // [4,2048,1024]
    const float* W_qkv  = (const float*)d_in[1];   // [3072,1024]
    const float* W_proj = (const float*)d_in[2];   // [1024,1024]
    float* out = (float*)d_out;                    // [4,2048,1024]

    __nv_bfloat16 *xh, *xl, *wqh, *wql, *wph, *wpl, *aoh, *aol;
    cudaGetSymbolAddress((void**)&xh,  g_xh);
    cudaGetSymbolAddress((void**)&xl,  g_xl);
    cudaGetSymbolAddress((void**)&wqh, g_wqh);
    cudaGetSymbolAddress((void**)&wql, g_wql);
    cudaGetSymbolAddress((void**)&wph, g_wph);
    cudaGetSymbolAddress((void**)&wpl, g_wpl);
    cudaGetSymbolAddress((void**)&aoh, g_aoh);
    cudaGetSymbolAddress((void**)&aol, g_aol);

    // 0) split inputs into bf16 hi/lo (vectorized by 4)
    {
        int n1 = MROWS * EMBED / 4, n2 = 3 * EMBED * EMBED / 4, n3 = EMBED * EMBED / 4;
        split_f32<<<(n1 + 255) / 256, 256>>>((const float4*)x, (uint2*)xh, (uint2*)xl, n1);
        split_f32<<<(n2 + 255) / 256, 256>>>((const float4*)W_qkv, (uint2*)wqh, (uint2*)wql, n2);
        split_f32<<<(n3 + 255) / 256, 256>>>((const float4*)W_proj, (uint2*)wph, (uint2*)wpl, n3);
    }

    // 1) QKV projection with split/scatter epilogue
    {
        cudaFuncSetAttribute((const void*)gemm_bf2<1>,
                             cudaFuncAttributeMaxDynamicSharedMemorySize, GEMM_SMEM);
        dim3 grid(3 * EMBED / 128, MROWS / 128);
        gemm_bf2<1><<<grid, 256, GEMM_SMEM>>>(xh, xl, wqh, wql, nullptr, EMBED, 3 * EMBED);
    }

    // 2) causal flash attention -> g_ao (split bf16)
    {
        cudaFuncSetAttribute((const void*)attn_bf2,
                             cudaFuncAttributeMaxDynamicSharedMemorySize, ATT_SMEM);
        dim3 grid(SEQ / 128, BATCH * NHEAD);
        attn_bf2<<<grid, 256, ATT_SMEM>>>();
    }

    // 3) output projection -> d_out (fp32)
    {
        cudaFuncSetAttribute((const void*)gemm_bf2<0>,
                             cudaFuncAttributeMaxDynamicSharedMemorySize, GEMM_SMEM);
        dim3 grid(EMBED / 128, MROWS / 128);
        gemm_bf2<0><<<grid, 256, GEMM_SMEM>>>(aoh, aol, wph, wpl, out, EMBED, EMBED);
    }
}